// round 9
// baseline (speedup 1.0000x reference)
#include <cuda_runtime.h>
#include <cstdint>

// ---------------- problem shapes ----------------
#define NT    64
#define NB    128
#define NF    4096
#define NH    2048
#define NOC   4
#define NSPL2 512
#define NOUT  10

#define K_MEM 0.1f
#define K_SYN 0.8f
#define V_TH  1.0f

typedef unsigned long long u64;

// Precomputed feedforward hidden currents: [t][b][c*2048 + h]
__device__ float g_cur[(size_t)NT * NB * NF];

// ---------------- packed f32x2 helpers (sm_100 baseline PTX) ----------------
__device__ __forceinline__ void upk2(u64 v, float& lo, float& hi) {
    asm("mov.b64 {%0, %1}, %2;" : "=f"(lo), "=f"(hi) : "l"(v));
}
__device__ __forceinline__ void fma2(u64& d, u64 a, u64 b) {
    asm("fma.rn.f32x2 %0, %1, %2, %0;" : "+l"(d) : "l"(a), "l"(b));
}

// ---------------------------------------------------------------------------
// Kernel 1: fp32 tiled GEMM, packed f32x2, zero inner-loop movs.
//   g_cur[(t*NB+b)*NF + c*NH + n] = sum_k x[...k] * W[c][k][n]
// M=8192/channel, N=2048, K=2048. BM=BN=128, BK=16, 256 threads, 8x8 tile.
// Accumulators packed over M-PAIRS: acc[(2i,2i+1)][n] += (a2i,a2i+1)*(bn,bn).
//   A [k][m] smem: m-consecutive pairs load directly as u64 (2-way conflicts).
//   B duplicated [k][2n]: (b,b) pairs load directly as u64 (2-way conflicts).
// Inner loop: 6x LDS.128 + 32x fma.rn.f32x2 per k-step per thread.
// ---------------------------------------------------------------------------
__global__ void __launch_bounds__(256, 2)
hidden_gemm_kernel(const float* __restrict__ X, const float* __restrict__ W) {
    const int c  = blockIdx.z;
    const int m0 = blockIdx.y * 128;
    const int n0 = blockIdx.x * 128;

    __shared__ float As[2][16][128];   // [k][m]           16 KB
    __shared__ float Bs[2][16][256];   // [k][2n] dup      32 KB  (total 48 KB)

    const int tid  = threadIdx.x;
    const int warp = tid >> 5;
    const int lane = tid & 31;

    // 16x16 thread grid; warp = 8 m-threads x 4 n-threads
    const int trow = (warp & 1) * 8 + (lane >> 2);   // 0..15
    const int tcol = (warp >> 1) * 4 + (lane & 3);   // 0..15

    const int aRow = tid >> 2;         // 0..63   (gmem A loader)
    const int aCol = (tid & 3) << 2;   // 0,4,8,12
    const int bRow = tid >> 5;         // 0..7    (gmem B loader)
    const int bCol = (tid & 31) << 2;  // 0..124

    const float* aPtr = X + (size_t)(m0 + aRow) * NF + (size_t)c * NH + aCol;
    const float* bPtr = W + ((size_t)c * NH + bRow) * NH + n0 + bCol;
    float*       cPtr = g_cur + (size_t)(m0 + trow * 8) * NF + (size_t)c * NH
                              + n0 + tcol * 8;

    // 4 packed m-pairs x 8 n columns (= 8x8 scalar tile)
    u64 acc[4][8];
#pragma unroll
    for (int i = 0; i < 4; i++)
#pragma unroll
        for (int j = 0; j < 8; j++) acc[i][j] = 0ull;

    // A: scalar transpose into [k][m]. B: duplicated (b,b) via float4 stores.
#define STORE_A(BUF, V0, V1)                                        \
    do {                                                            \
        As[BUF][aCol + 0][aRow]      = (V0).x;                      \
        As[BUF][aCol + 1][aRow]      = (V0).y;                      \
        As[BUF][aCol + 2][aRow]      = (V0).z;                      \
        As[BUF][aCol + 3][aRow]      = (V0).w;                      \
        As[BUF][aCol + 0][aRow + 64] = (V1).x;                      \
        As[BUF][aCol + 1][aRow + 64] = (V1).y;                      \
        As[BUF][aCol + 2][aRow + 64] = (V1).z;                      \
        As[BUF][aCol + 3][aRow + 64] = (V1).w;                      \
    } while (0)
#define STORE_B(BUF, V0, V1)                                                        \
    do {                                                                            \
        *(float4*)&Bs[BUF][bRow][2 * bCol]         = make_float4((V0).x, (V0).x, (V0).y, (V0).y); \
        *(float4*)&Bs[BUF][bRow][2 * bCol + 4]     = make_float4((V0).z, (V0).z, (V0).w, (V0).w); \
        *(float4*)&Bs[BUF][bRow + 8][2 * bCol]     = make_float4((V1).x, (V1).x, (V1).y, (V1).y); \
        *(float4*)&Bs[BUF][bRow + 8][2 * bCol + 4] = make_float4((V1).z, (V1).z, (V1).w, (V1).w); \
    } while (0)

    // Prologue: k-tile 0 -> buffer 0
    {
        float4 a0 = *(const float4*)(aPtr);
        float4 a1 = *(const float4*)(aPtr + (size_t)64 * NF);
        float4 b0 = *(const float4*)(bPtr);
        float4 b1 = *(const float4*)(bPtr + (size_t)8 * NH);
        STORE_A(0, a0, a1);
        STORE_B(0, b0, b1);
    }
    __syncthreads();

    int buf = 0;
    const int KT = NH / 16;   // 128 k-tiles
    for (int kt = 0; kt < KT; ++kt) {
        float4 a0, a1, b0, b1;
        const bool pre = (kt + 1 < KT);
        if (pre) {
            const int k0 = (kt + 1) * 16;
            a0 = *(const float4*)(aPtr + k0);
            a1 = *(const float4*)(aPtr + (size_t)64 * NF + k0);
            b0 = *(const float4*)(bPtr + (size_t)k0 * NH);
            b1 = *(const float4*)(bPtr + (size_t)(k0 + 8) * NH);
        }
#pragma unroll
        for (int kk = 0; kk < 16; ++kk) {
            // A m-pairs: 2x LDS.128 -> 4 u64 pairs (a_{2i}, a_{2i+1})
            const ulonglong2* apd = (const ulonglong2*)&As[buf][kk][trow * 8];
            const ulonglong2 ap0 = apd[0], ap1 = apd[1];
            // B dup-pairs: 4x LDS.128 -> 8 u64 pairs (b_n, b_n)
            const ulonglong2* bpd = (const ulonglong2*)&Bs[buf][kk][tcol * 16];
            const ulonglong2 bp0 = bpd[0], bp1 = bpd[1],
                             bp2 = bpd[2], bp3 = bpd[3];

            const u64 a2[4] = {ap0.x, ap0.y, ap1.x, ap1.y};
            const u64 b2[8] = {bp0.x, bp0.y, bp1.x, bp1.y,
                               bp2.x, bp2.y, bp3.x, bp3.y};
#pragma unroll
            for (int i = 0; i < 4; i++)
#pragma unroll
                for (int j = 0; j < 8; j++) fma2(acc[i][j], a2[i], b2[j]);
        }
        if (pre) {
            const int nb = buf ^ 1;
            STORE_A(nb, a0, a1);
            STORE_B(nb, b0, b1);
        }
        __syncthreads();
        buf ^= 1;
    }

    // Epilogue: acc[i][j] = (row 2i, row 2i+1) of column j. Unpack and store
    // each row as two float4s.
#pragma unroll
    for (int i = 0; i < 4; i++) {
        float lo[8], hi[8];
#pragma unroll
        for (int j = 0; j < 8; j++) upk2(acc[i][j], lo[j], hi[j]);
        float* cp0 = cPtr + (size_t)(2 * i) * NF;
        float* cp1 = cPtr + (size_t)(2 * i + 1) * NF;
        *(float4*)(cp0)     = make_float4(lo[0], lo[1], lo[2], lo[3]);
        *(float4*)(cp0 + 4) = make_float4(lo[4], lo[5], lo[6], lo[7]);
        *(float4*)(cp1)     = make_float4(hi[0], hi[1], hi[2], hi[3]);
        *(float4*)(cp1 + 4) = make_float4(hi[4], hi[5], hi[6], hi[7]);
    }
#undef STORE_A
#undef STORE_B
}

// ---------------------------------------------------------------------------
// Kernel 2: persistent per-sample recurrence (identical to R4/R7 passing
// version: 128 blocks x 512 threads, all state + w_out slice in registers).
// ---------------------------------------------------------------------------
__global__ void __launch_bounds__(512, 1)
recur_kernel(const float* __restrict__ w_out, float* __restrict__ out) {
    __shared__ float wsum[16 * NOUT];
    __shared__ float so[NOC * NOUT];

    const int b    = blockIdx.x;
    const int tid  = threadIdx.x;
    const int lane = tid & 31;
    const int warp = tid >> 5;

    const int myc  = tid >> 7;
    const int irow = (tid << 2) & 511;

    float wr[4][NOUT];
#pragma unroll
    for (int j = 0; j < 4; j++)
#pragma unroll
        for (int o = 0; o < NOUT; o++)
            wr[j][o] = __ldg(&w_out[((size_t)myc * NSPL2 + irow + j) * NOUT + o]);

    float vd0[4] = {0, 0, 0, 0}, id0v[4] = {0, 0, 0, 0};
    float vd1[4] = {0, 0, 0, 0}, id1v[4] = {0, 0, 0, 0};
    float vsh[4] = {0, 0, 0, 0}, ish[4]  = {0, 0, 0, 0};
    float vdo = 0.f, ido = 0.f;
    float vso = 0.f, iso = 0.f;

    const float* curp = g_cur + (size_t)b * NF + (tid << 2);

    float4 c0 = *(const float4*)(curp);
    float4 c1 = *(const float4*)(curp + NH);

    const int oc = tid / 10;
    const int oo = tid - oc * 10;

    for (int t = 0; t < NT; ++t) {
        float4 n0v, n1v;
        if (t + 1 < NT) {
            const float* p = curp + (size_t)(t + 1) * NB * NF;
            n0v = *(const float4*)(p);
            n1v = *(const float4*)(p + NH);
        }

        const float cu0[4] = {c0.x, c0.y, c0.z, c0.w};
        const float cu1[4] = {c1.x, c1.y, c1.z, c1.w};

        float acc[NOUT];
#pragma unroll
        for (int o = 0; o < NOUT; o++) acc[o] = 0.f;

#pragma unroll
        for (int j = 0; j < 4; j++) {
            float sd = 0.f;
            {
                const float v = vd0[j], i = id0v[j];
                const float vdec = v + K_MEM * (i - v);
                sd += (vdec > V_TH) ? 1.f : 0.f;
                vd0[j]  = (vdec > V_TH) ? 0.f : vdec;
                id0v[j] = i * K_SYN + cu0[j];
            }
            {
                const float v = vd1[j], i = id1v[j];
                const float vdec = v + K_MEM * (i - v);
                sd += (vdec > V_TH) ? 1.f : 0.f;
                vd1[j]  = (vdec > V_TH) ? 0.f : vdec;
                id1v[j] = i * K_SYN + cu1[j];
            }
            {
                const float v = vsh[j], i = ish[j];
                const float vdec = v + K_MEM * (i - v);
                const bool  z = (vdec > V_TH);
                vsh[j] = z ? 0.f : vdec;
                ish[j] = i * K_SYN + sd;
                if (z) {
#pragma unroll
                    for (int o = 0; o < NOUT; o++) acc[o] += wr[j][o];
                }
            }
        }

#pragma unroll
        for (int o = 0; o < NOUT; o++) {
            float v = acc[o];
            v += __shfl_xor_sync(0xffffffffu, v, 16);
            v += __shfl_xor_sync(0xffffffffu, v, 8);
            v += __shfl_xor_sync(0xffffffffu, v, 4);
            v += __shfl_xor_sync(0xffffffffu, v, 2);
            v += __shfl_xor_sync(0xffffffffu, v, 1);
            acc[o] = v;
        }
        if (lane == 0) {
#pragma unroll
            for (int o = 0; o < NOUT; o++) wsum[warp * NOUT + o] = acc[o];
        }
        __syncthreads();

        if (tid < NOC * NOUT) {
            const float cur = wsum[(4 * oc + 0) * NOUT + oo]
                            + wsum[(4 * oc + 1) * NOUT + oo]
                            + wsum[(4 * oc + 2) * NOUT + oo]
                            + wsum[(4 * oc + 3) * NOUT + oo];
            const float vdec = vdo + K_MEM * (ido - vdo);
            const bool  z = (vdec > V_TH);
            vdo = z ? 0.f : vdec;
            ido = ido * K_SYN + cur;
            so[tid] = z ? 1.f : 0.f;
        }
        __syncthreads();

        if (tid < NOUT) {
            const float ssum = so[tid] + so[tid + 10] + so[tid + 20] + so[tid + 30];
            const float vnew = vso + K_MEM * (iso - vso);
            iso = iso * K_SYN + ssum;
            vso = vnew;
            out[((size_t)t * NB + b) * NOUT + tid] = vnew;
        }
        __syncthreads();

        if (t + 1 < NT) { c0 = n0v; c1 = n1v; }
    }
}

// ---------------------------------------------------------------------------
extern "C" void kernel_launch(void* const* d_in, const int* in_sizes, int n_in,
                              void* d_out, int out_size) {
    const float* x  = nullptr;
    const float* wh = nullptr;
    const float* wo = nullptr;
    for (int i = 0; i < n_in; ++i) {
        if (in_sizes[i] == 33554432)     x  = (const float*)d_in[i];
        else if (in_sizes[i] == 8388608) wh = (const float*)d_in[i];
        else if (in_sizes[i] == 20480)   wo = (const float*)d_in[i];
    }
    float* out = (float*)d_out;

    dim3 g(NH / 128, (NT * NB) / 128, 2);
    hidden_gemm_kernel<<<g, 256>>>(x, wh);

    recur_kernel<<<NB, 512>>>(wo, out);
}

// round 10
// speedup vs baseline: 2.0234x; 2.0234x over previous
#include <cuda_runtime.h>
#include <cuda_bf16.h>
#include <cstdint>

// ---------------- problem shapes ----------------
#define NT    64
#define NB    128
#define NF    4096
#define NH    2048
#define NOC   4
#define NSPL2 512
#define NOUT  10

#define K_MEM 0.1f
#define K_SYN 0.8f
#define V_TH  1.0f

// ---------------- scratch ----------------
// Hidden currents [t*B + b][c*2048 + h]
__device__ float g_cur[(size_t)NT * NB * NF];
// bf16 3-way split of w_hidden, TRANSPOSED to [c][n][k]
__device__ __nv_bfloat16 g_wth[(size_t)2 * NH * NH];
__device__ __nv_bfloat16 g_wtm[(size_t)2 * NH * NH];
__device__ __nv_bfloat16 g_wtl[(size_t)2 * NH * NH];

// Exact 3-way bf16 split: h+m+l reproduces all 24 fp32 mantissa bits
// (Dekker-split subtractions are exact in fp32).
__device__ __forceinline__ void bf16_split3(float v, __nv_bfloat16& h,
                                            __nv_bfloat16& m, __nv_bfloat16& l) {
    h = __float2bfloat16_rn(v);
    const float r1 = v - __bfloat162float(h);
    m = __float2bfloat16_rn(r1);
    const float r2 = r1 - __bfloat162float(m);
    l = __float2bfloat16_rn(r2);
}

// mma.sync m16n8k16 row.col bf16 -> f32 (sm_80 baseline PTX; HMMA on sm_100)
__device__ __forceinline__ void mma_bf16(float* cc, const uint32_t* a,
                                         uint32_t b0, uint32_t b1) {
    asm volatile(
        "mma.sync.aligned.m16n8k16.row.col.f32.bf16.bf16.f32 "
        "{%0,%1,%2,%3}, {%4,%5,%6,%7}, {%8,%9}, {%0,%1,%2,%3};"
        : "+f"(cc[0]), "+f"(cc[1]), "+f"(cc[2]), "+f"(cc[3])
        : "r"(a[0]), "r"(a[1]), "r"(a[2]), "r"(a[3]), "r"(b0), "r"(b1));
}

// ---------------------------------------------------------------------------
// Prep: transpose + 3-way-split w_hidden [c][k][n] -> g_wt{h,m,l}[c][n][k]
// ---------------------------------------------------------------------------
__global__ void split_wt_kernel(const float* __restrict__ w) {
    __shared__ float t[32][33];
    const int c  = blockIdx.z;
    const int bx = blockIdx.x;      // n-tile
    const int by = blockIdx.y;      // k-tile
    const int tx = threadIdx.x, ty = threadIdx.y;

#pragma unroll
    for (int j = 0; j < 4; j++) {
        const int k = by * 32 + ty + j * 8;
        const int n = bx * 32 + tx;
        t[ty + j * 8][tx] = w[((size_t)c * NH + k) * NH + n];
    }
    __syncthreads();
#pragma unroll
    for (int j = 0; j < 4; j++) {
        const int n = bx * 32 + ty + j * 8;
        const int k = by * 32 + tx;
        __nv_bfloat16 h, m, l;
        bf16_split3(t[tx][ty + j * 8], h, m, l);
        const size_t o = ((size_t)c * NH + n) * NH + k;
        g_wth[o] = h;
        g_wtm[o] = m;
        g_wtl[o] = l;
    }
}

// ---------------------------------------------------------------------------
// Kernel 1: bf16x3-split tensor-core GEMM (6 mma passes, fp32-exact class).
//   g_cur[m][c*NH + n] = sum_k X[m][c*NH + k] * W[c][k][n]
// M=8192/channel, N=2048, K=2048. Tile 128x128, BK=16, 256 threads (8 warps
// as 2m x 4n, warp tile 64x32 = 4 m-frags x 4 n-frags of m16n8k16).
// A split on-the-fly from fp32 x; B from pre-split transposed weights.
// Smem rows padded to 24 bf16 (48 B) -> conflict-free fragment loads.
// ---------------------------------------------------------------------------
__global__ void __launch_bounds__(256, 2)
gemm_bf16x3_kernel(const float* __restrict__ X) {
    __shared__ alignas(16) __nv_bfloat16 As[3][128][24];   // 18 KB
    __shared__ alignas(16) __nv_bfloat16 Bs[3][128][24];   // 18 KB

    const int c  = blockIdx.z;
    const int m0 = blockIdx.y * 128;
    const int n0 = blockIdx.x * 128;

    const int tid  = threadIdx.x;
    const int wid  = tid >> 5;
    const int lane = tid & 31;
    const int wm   = wid & 1;          // warp m index (0..1)
    const int wn   = wid >> 1;         // warp n index (0..3)
    const int r    = lane >> 2;        // fragment row group 0..7
    const int q    = (lane & 3) * 2;   // fragment k/col pair base

    // Loader mapping: 2 threads per row, each handles 8 elements (16 B bf16)
    const int mrow = tid >> 1;         // 0..127
    const int half = tid & 1;          // 0..1

    const float* aP = X + (size_t)(m0 + mrow) * NF + (size_t)c * NH + half * 8;
    const size_t bOff = ((size_t)c * NH + n0 + mrow) * NH + half * 8;
    const __nv_bfloat16* bPh = g_wth + bOff;
    const __nv_bfloat16* bPm = g_wtm + bOff;
    const __nv_bfloat16* bPl = g_wtl + bOff;

    float acc[4][4][4];                // [m-frag][n-frag][c0..c3]
#pragma unroll
    for (int i = 0; i < 4; i++)
#pragma unroll
        for (int j = 0; j < 4; j++)
#pragma unroll
            for (int e = 0; e < 4; e++) acc[i][j][e] = 0.f;

    for (int kt = 0; kt < NH / 16; ++kt) {
        __syncthreads();               // previous compute done reading smem
        {
            // A: read 8 fp32, split to 3x8 bf16, store
            const float4 v0 = *(const float4*)(aP + kt * 16);
            const float4 v1 = *(const float4*)(aP + kt * 16 + 4);
            const float tv[8] = {v0.x, v0.y, v0.z, v0.w,
                                 v1.x, v1.y, v1.z, v1.w};
            alignas(16) __nv_bfloat16 th[8], tm[8], tl[8];
#pragma unroll
            for (int i = 0; i < 8; i++) bf16_split3(tv[i], th[i], tm[i], tl[i]);
            *(uint4*)&As[0][mrow][half * 8] = *(const uint4*)th;
            *(uint4*)&As[1][mrow][half * 8] = *(const uint4*)tm;
            *(uint4*)&As[2][mrow][half * 8] = *(const uint4*)tl;
            // B: straight bf16 copies from pre-split transposed weights
            *(uint4*)&Bs[0][mrow][half * 8] = *(const uint4*)(bPh + kt * 16);
            *(uint4*)&Bs[1][mrow][half * 8] = *(const uint4*)(bPm + kt * 16);
            *(uint4*)&Bs[2][mrow][half * 8] = *(const uint4*)(bPl + kt * 16);
        }
        __syncthreads();

        // 6 split-pass combinations: (sA, sB) with sA + sB <= 2
#pragma unroll
        for (int s = 0; s < 3; ++s) {
            uint32_t Af[4][4];
#pragma unroll
            for (int mf = 0; mf < 4; mf++) {
                const int rb = wm * 64 + mf * 16;
                Af[mf][0] = *(const uint32_t*)&As[s][rb + r][q];
                Af[mf][1] = *(const uint32_t*)&As[s][rb + 8 + r][q];
                Af[mf][2] = *(const uint32_t*)&As[s][rb + r][q + 8];
                Af[mf][3] = *(const uint32_t*)&As[s][rb + 8 + r][q + 8];
            }
#pragma unroll
            for (int sb = 0; sb < 3 - s; ++sb) {
#pragma unroll
                for (int nf = 0; nf < 4; nf++) {
                    const int nb = wn * 32 + nf * 8;
                    const uint32_t b0 = *(const uint32_t*)&Bs[sb][nb + r][q];
                    const uint32_t b1 = *(const uint32_t*)&Bs[sb][nb + r][q + 8];
#pragma unroll
                    for (int mf = 0; mf < 4; mf++)
                        mma_bf16(acc[mf][nf], Af[mf], b0, b1);
                }
            }
        }
    }

    // Epilogue: C frag c0,c1 = C[row][col,col+1]; c2,c3 = C[row+8][col,col+1]
#pragma unroll
    for (int mf = 0; mf < 4; mf++) {
#pragma unroll
        for (int nf = 0; nf < 4; nf++) {
            const int row0 = m0 + wm * 64 + mf * 16 + r;
            const size_t colg = (size_t)c * NH + n0 + wn * 32 + nf * 8 + q;
            *(float2*)&g_cur[(size_t)row0 * NF + colg] =
                make_float2(acc[mf][nf][0], acc[mf][nf][1]);
            *(float2*)&g_cur[(size_t)(row0 + 8) * NF + colg] =
                make_float2(acc[mf][nf][2], acc[mf][nf][3]);
        }
    }
}

// ---------------------------------------------------------------------------
// Kernel 2: persistent per-sample recurrence (identical to R4/R7 passing
// version: 128 blocks x 512 threads, all state + w_out slice in registers).
// ---------------------------------------------------------------------------
__global__ void __launch_bounds__(512, 1)
recur_kernel(const float* __restrict__ w_out, float* __restrict__ out) {
    __shared__ float wsum[16 * NOUT];
    __shared__ float so[NOC * NOUT];

    const int b    = blockIdx.x;
    const int tid  = threadIdx.x;
    const int lane = tid & 31;
    const int warp = tid >> 5;

    const int myc  = tid >> 7;
    const int irow = (tid << 2) & 511;

    float wr[4][NOUT];
#pragma unroll
    for (int j = 0; j < 4; j++)
#pragma unroll
        for (int o = 0; o < NOUT; o++)
            wr[j][o] = __ldg(&w_out[((size_t)myc * NSPL2 + irow + j) * NOUT + o]);

    float vd0[4] = {0, 0, 0, 0}, id0v[4] = {0, 0, 0, 0};
    float vd1[4] = {0, 0, 0, 0}, id1v[4] = {0, 0, 0, 0};
    float vsh[4] = {0, 0, 0, 0}, ish[4]  = {0, 0, 0, 0};
    float vdo = 0.f, ido = 0.f;
    float vso = 0.f, iso = 0.f;

    const float* curp = g_cur + (size_t)b * NF + (tid << 2);

    float4 c0 = *(const float4*)(curp);
    float4 c1 = *(const float4*)(curp + NH);

    const int oc = tid / 10;
    const int oo = tid - oc * 10;

    for (int t = 0; t < NT; ++t) {
        float4 n0v, n1v;
        if (t + 1 < NT) {
            const float* p = curp + (size_t)(t + 1) * NB * NF;
            n0v = *(const float4*)(p);
            n1v = *(const float4*)(p + NH);
        }

        const float cu0[4] = {c0.x, c0.y, c0.z, c0.w};
        const float cu1[4] = {c1.x, c1.y, c1.z, c1.w};

        float acc[NOUT];
#pragma unroll
        for (int o = 0; o < NOUT; o++) acc[o] = 0.f;

#pragma unroll
        for (int j = 0; j < 4; j++) {
            float sd = 0.f;
            {
                const float v = vd0[j], i = id0v[j];
                const float vdec = v + K_MEM * (i - v);
                sd += (vdec > V_TH) ? 1.f : 0.f;
                vd0[j]  = (vdec > V_TH) ? 0.f : vdec;
                id0v[j] = i * K_SYN + cu0[j];
            }
            {
                const float v = vd1[j], i = id1v[j];
                const float vdec = v + K_MEM * (i - v);
                sd += (vdec > V_TH) ? 1.f : 0.f;
                vd1[j]  = (vdec > V_TH) ? 0.f : vdec;
                id1v[j] = i * K_SYN + cu1[j];
            }
            {
                const float v = vsh[j], i = ish[j];
                const float vdec = v + K_MEM * (i - v);
                const bool  z = (vdec > V_TH);
                vsh[j] = z ? 0.f : vdec;
                ish[j] = i * K_SYN + sd;
                if (z) {
#pragma unroll
                    for (int o = 0; o < NOUT; o++) acc[o] += wr[j][o];
                }
            }
        }

#pragma unroll
        for (int o = 0; o < NOUT; o++) {
            float v = acc[o];
            v += __shfl_xor_sync(0xffffffffu, v, 16);
            v += __shfl_xor_sync(0xffffffffu, v, 8);
            v += __shfl_xor_sync(0xffffffffu, v, 4);
            v += __shfl_xor_sync(0xffffffffu, v, 2);
            v += __shfl_xor_sync(0xffffffffu, v, 1);
            acc[o] = v;
        }
        if (lane == 0) {
#pragma unroll
            for (int o = 0; o < NOUT; o++) wsum[warp * NOUT + o] = acc[o];
        }
        __syncthreads();

        if (tid < NOC * NOUT) {
            const float cur = wsum[(4 * oc + 0) * NOUT + oo]
                            + wsum[(4 * oc + 1) * NOUT + oo]
                            + wsum[(4 * oc + 2) * NOUT + oo]
                            + wsum[(4 * oc + 3) * NOUT + oo];
            const float vdec = vdo + K_MEM * (ido - vdo);
            const bool  z = (vdec > V_TH);
            vdo = z ? 0.f : vdec;
            ido = ido * K_SYN + cur;
            so[tid] = z ? 1.f : 0.f;
        }
        __syncthreads();

        if (tid < NOUT) {
            const float ssum = so[tid] + so[tid + 10] + so[tid + 20] + so[tid + 30];
            const float vnew = vso + K_MEM * (iso - vso);
            iso = iso * K_SYN + ssum;
            vso = vnew;
            out[((size_t)t * NB + b) * NOUT + tid] = vnew;
        }
        __syncthreads();

        if (t + 1 < NT) { c0 = n0v; c1 = n1v; }
    }
}

// ---------------------------------------------------------------------------
extern "C" void kernel_launch(void* const* d_in, const int* in_sizes, int n_in,
                              void* d_out, int out_size) {
    const float* x  = nullptr;
    const float* wh = nullptr;
    const float* wo = nullptr;
    for (int i = 0; i < n_in; ++i) {
        if (in_sizes[i] == 33554432)     x  = (const float*)d_in[i];
        else if (in_sizes[i] == 8388608) wh = (const float*)d_in[i];
        else if (in_sizes[i] == 20480)   wo = (const float*)d_in[i];
    }
    float* out = (float*)d_out;

    // Weight transpose + 3-way bf16 split (runs once per call, ~20us)
    dim3 tg(NH / 32, NH / 32, 2);
    split_wt_kernel<<<tg, dim3(32, 8)>>>(wh);

    // Tensor-core split GEMM: grid (16 n-tiles, 64 m-tiles, 2 channels)
    dim3 gg(NH / 128, (NT * NB) / 128, 2);
    gemm_bf16x3_kernel<<<gg, 256>>>(x);

    // Persistent recurrence, one block per batch sample
    recur_kernel<<<NB, 512>>>(wo, out);
}